// round 9
// baseline (speedup 1.0000x reference)
#include <cuda_runtime.h>

// NeuralODE: encoder -> 99 RK4 steps -> decoder at every timestep.
// Lane-pair split (S=2) x 2 elements per pair (E=2): 2048 warps at halved
// per-element LDS traffic. THIS REV: single-wave residency -- zn moved to
// padded smem (saves 32 regs), __launch_bounds__(64,7) => 7 blocks/SM,
// 148*7=1036 >= 1024 blocks, 14 warps/SM (R6 ran 2 waves at 5 blocks/SM).

#define HID 50
#define LAT 16

typedef unsigned long long u64;

__device__ __forceinline__ u64 pk2(float a, float b) {
    u64 v; asm("mov.b64 %0, {%1,%2};" : "=l"(v) : "f"(a), "f"(b)); return v;
}
__device__ __forceinline__ float2 up2(u64 v) {
    float2 r; asm("mov.b64 {%0,%1}, %2;" : "=f"(r.x), "=f"(r.y) : "l"(v)); return r;
}
__device__ __forceinline__ u64 ffma2(u64 a, u64 b, u64 c) {
    u64 d; asm("fma.rn.f32x2 %0, %1, %2, %3;" : "=l"(d) : "l"(a), "l"(b), "l"(c)); return d;
}
__device__ __forceinline__ u64 fmul2(u64 a, u64 b) {
    u64 d; asm("mul.rn.f32x2 %0, %1, %2;" : "=l"(d) : "l"(a), "l"(b)); return d;
}
__device__ __forceinline__ u64 fadd2(u64 a, u64 b) {
    u64 d; asm("add.rn.f32x2 %0, %1, %2;" : "=l"(d) : "l"(a), "l"(b)); return d;
}

// tanh(x) = 1 - 2/(1+e^{2x});  ~1e-6 rel err, saturates correctly.
__device__ __forceinline__ float tanh_fast(float x) {
    float e = __expf(2.0f * x);
    return 1.0f - __fdividef(2.0f, e + 1.0f);
}

struct __align__(16) SW {
    float wo1t[HID * LAT];  // wo1t[i*16+k] = Wo1[k][i]
    float wo2 [HID * LAT];  // Wo2[i][j], row-major
    float we2 [HID * LAT];  // We2[i][k], row-major
    float wd1t[HID * LAT];  // wd1t[i*16+k] = Wd1[k][i]
    float bo2[LAT];
    float be2[LAT];
    float bo1[HID];
    float be1[HID];
    float bd1[HID];
    float we1a[HID];
    float we1b[HID];
    float wd2[HID];
    float dt[128];
    float bd2;
};

// dot of 16-dim packed z with a weight row already in registers
__device__ __forceinline__ float rdot(const u64 zp[8], ulonglong2 w0, ulonglong2 w1,
                                      ulonglong2 w2, ulonglong2 w3) {
    u64 a0 = fmul2(zp[0], w0.x);
    u64 a1 = fmul2(zp[1], w0.y);
    a0 = ffma2(zp[2], w1.x, a0);
    a1 = ffma2(zp[3], w1.y, a1);
    a0 = ffma2(zp[4], w2.x, a0);
    a1 = ffma2(zp[5], w2.y, a1);
    a0 = ffma2(zp[6], w3.x, a0);
    a1 = ffma2(zp[7], w3.y, a1);
    float2 p = up2(fadd2(a0, a1));
    return p.x + p.y;
}

// Partial f over this lane's 25 hidden units for BOTH elements,
// then combine partial k across the lane pair (shfl_xor 16).
__device__ __forceinline__ void ode_f2(const u64 zA[8], const u64 zB[8],
                                       u64 kA[8], u64 kB[8], const SW& s,
                                       int i0, int half) {
    const u64* bo2p = (const u64*)s.bo2;
#pragma unroll
    for (int j = 0; j < 8; j++) {
        kA[j] = half ? 0ull : bo2p[j];
        kB[j] = kA[j];
    }
#pragma unroll 5
    for (int ii = 0; ii < HID / 2; ii++) {
        int i = i0 + ii;
        const ulonglong2* w = (const ulonglong2*)(s.wo1t + i * LAT);
        ulonglong2 w0 = w[0], w1 = w[1], w2 = w[2], w3 = w[3];
        float b1 = s.bo1[i];
        float hA = tanh_fast(rdot(zA, w0, w1, w2, w3) + b1);
        float hB = tanh_fast(rdot(zB, w0, w1, w2, w3) + b1);
        u64 hA2 = pk2(hA, hA), hB2 = pk2(hB, hB);
        const ulonglong2* v = (const ulonglong2*)(s.wo2 + i * LAT);
#pragma unroll
        for (int j = 0; j < 4; j++) {
            ulonglong2 vv = v[j];
            kA[2 * j]     = ffma2(hA2, vv.x, kA[2 * j]);
            kA[2 * j + 1] = ffma2(hA2, vv.y, kA[2 * j + 1]);
            kB[2 * j]     = ffma2(hB2, vv.x, kB[2 * j]);
            kB[2 * j + 1] = ffma2(hB2, vv.y, kB[2 * j + 1]);
        }
    }
#pragma unroll
    for (int j = 0; j < 8; j++) {
        kA[j] = fadd2(kA[j], __shfl_xor_sync(0xffffffffu, kA[j], 16));
        kB[j] = fadd2(kB[j], __shfl_xor_sync(0xffffffffu, kB[j], 16));
    }
}

// Partial decode over this lane's 25 hidden units, combined across pair.
__device__ __forceinline__ float2 decode2(const u64 zA[8], const u64 zB[8],
                                          const SW& s, int i0, int half) {
    float yA = half ? 0.0f : s.bd2;
    float yB = yA;
#pragma unroll 5
    for (int ii = 0; ii < HID / 2; ii++) {
        int i = i0 + ii;
        const ulonglong2* w = (const ulonglong2*)(s.wd1t + i * LAT);
        ulonglong2 w0 = w[0], w1 = w[1], w2 = w[2], w3 = w[3];
        float b1 = s.bd1[i], wd = s.wd2[i];
        float hA = fmaxf(rdot(zA, w0, w1, w2, w3) + b1, 0.0f);
        float hB = fmaxf(rdot(zB, w0, w1, w2, w3) + b1, 0.0f);
        yA = fmaf(hA, wd, yA);
        yB = fmaf(hB, wd, yB);
    }
    yA += __shfl_xor_sync(0xffffffffu, yA, 16);
    yB += __shfl_xor_sync(0xffffffffu, yB, 16);
    return make_float2(yA, yB);
}

__global__ void __launch_bounds__(64, 7)
node_kernel(const float* __restrict__ x0, const float* __restrict__ t,
            const float* __restrict__ We1, const float* __restrict__ be1,
            const float* __restrict__ We2, const float* __restrict__ be2,
            const float* __restrict__ Wo1, const float* __restrict__ bo1,
            const float* __restrict__ Wo2, const float* __restrict__ bo2,
            const float* __restrict__ Wd1, const float* __restrict__ bd1,
            const float* __restrict__ Wd2, const float* __restrict__ bd2,
            float* __restrict__ out, int Bn, int Tn) {
    __shared__ SW s;
    // zn accumulator, thread-private slots, padded stride 9 (conflict-free LDS.128)
    __shared__ ulonglong2 znb[64][9];   // [tid][0..3]=elem A, [4..7]=elem B
    int tid = threadIdx.x;

    for (int idx = tid; idx < HID * LAT; idx += blockDim.x) {
        int i = idx >> 4, k = idx & 15;
        s.wo1t[idx] = Wo1[k * HID + i];
        s.wd1t[idx] = Wd1[k * HID + i];
        s.wo2[idx]  = Wo2[idx];
        s.we2[idx]  = We2[idx];
    }
    for (int idx = tid; idx < HID; idx += blockDim.x) {
        s.bo1[idx]  = bo1[idx];
        s.be1[idx]  = be1[idx];
        s.bd1[idx]  = bd1[idx];
        s.we1a[idx] = We1[idx];
        s.we1b[idx] = We1[HID + idx];
        s.wd2[idx]  = Wd2[idx];
    }
    for (int idx = tid; idx < LAT; idx += blockDim.x) {
        s.bo2[idx] = bo2[idx];
        s.be2[idx] = be2[idx];
    }
    for (int idx = tid; idx < Tn - 1 && idx < 128; idx += blockDim.x)
        s.dt[idx] = t[idx + 1] - t[idx];
    if (tid == 0) s.bd2 = bd2[0];
    __syncthreads();

    int warp = tid >> 5, lane = tid & 31;
    int half = lane >> 4;              // which 25 hidden units this lane owns
    int i0   = half * (HID / 2);
    int wb   = (blockIdx.x * 2 + warp) * 32;   // 32 elements per warp
    int eA = wb + (lane & 15);
    int eB = eA + 16;
    bool vA = (eA < Bn), vB = (eB < Bn);
    int cA = vA ? eA : (Bn - 1);
    int cB = vB ? eB : (Bn - 1);

    // ---------- Encoder (one-time): full 50-unit loop, both elements ----
    float2 xA = ((const float2*)x0)[cA];
    float2 xB = ((const float2*)x0)[cB];
    u64 zA[8], zB[8];
    {
        const u64* be2p = (const u64*)s.be2;
#pragma unroll
        for (int j = 0; j < 8; j++) { zA[j] = be2p[j]; zB[j] = be2p[j]; }
#pragma unroll 5
        for (int i = 0; i < HID; i++) {
            float w1a = s.we1a[i], w1b = s.we1b[i], b1 = s.be1[i];
            float hA = fmaxf(fmaf(xA.y, w1b, fmaf(xA.x, w1a, b1)), 0.0f);
            float hB = fmaxf(fmaf(xB.y, w1b, fmaf(xB.x, w1a, b1)), 0.0f);
            u64 hA2 = pk2(hA, hA), hB2 = pk2(hB, hB);
            const ulonglong2* w = (const ulonglong2*)(s.we2 + i * LAT);
#pragma unroll
            for (int j = 0; j < 4; j++) {
                ulonglong2 ww = w[j];
                zA[2 * j]     = ffma2(hA2, ww.x, zA[2 * j]);
                zA[2 * j + 1] = ffma2(hA2, ww.y, zA[2 * j + 1]);
                zB[2 * j]     = ffma2(hB2, ww.x, zB[2 * j]);
                zB[2 * j + 1] = ffma2(hB2, ww.y, zB[2 * j + 1]);
            }
        }
    }

    {
        float2 y = decode2(zA, zB, s, i0, half);
        if (half == 0) {
            if (vA) out[eA] = y.x;
            if (vB) out[eB] = y.y;
        }
    }

    // ---------- RK4 time stepping ----------
    for (int st = 0; st < Tn - 1; ++st) {
        float dt = s.dt[st];
        float h6 = dt * (1.0f / 6.0f);
        float h3 = dt * (1.0f / 3.0f);
        float hf = dt * 0.5f;
        u64 c6 = pk2(h6, h6), c3 = pk2(h3, h3), c2 = pk2(hf, hf), c1 = pk2(dt, dt);

        u64 ztA[8], ztB[8], kA[8], kB[8];

        // stage 1: zn = z + c6*k1 (store), zt = z + c2*k1
        ode_f2(zA, zB, kA, kB, s, i0, half);
#pragma unroll
        for (int j2 = 0; j2 < 4; j2++) {
            znb[tid][j2]     = make_ulonglong2(ffma2(c6, kA[2*j2],   zA[2*j2]),
                                               ffma2(c6, kA[2*j2+1], zA[2*j2+1]));
            znb[tid][j2 + 4] = make_ulonglong2(ffma2(c6, kB[2*j2],   zB[2*j2]),
                                               ffma2(c6, kB[2*j2+1], zB[2*j2+1]));
        }
#pragma unroll
        for (int j = 0; j < 8; j++) {
            ztA[j] = ffma2(c2, kA[j], zA[j]);
            ztB[j] = ffma2(c2, kB[j], zB[j]);
        }

        // stage 2: zn += c3*k2, zt = z + c2*k2
        ode_f2(ztA, ztB, kA, kB, s, i0, half);
#pragma unroll
        for (int j2 = 0; j2 < 4; j2++) {
            ulonglong2 a = znb[tid][j2], b = znb[tid][j2 + 4];
            a.x = ffma2(c3, kA[2*j2], a.x);   a.y = ffma2(c3, kA[2*j2+1], a.y);
            b.x = ffma2(c3, kB[2*j2], b.x);   b.y = ffma2(c3, kB[2*j2+1], b.y);
            znb[tid][j2] = a; znb[tid][j2 + 4] = b;
        }
#pragma unroll
        for (int j = 0; j < 8; j++) {
            ztA[j] = ffma2(c2, kA[j], zA[j]);
            ztB[j] = ffma2(c2, kB[j], zB[j]);
        }

        // stage 3: zn += c3*k3, zt = z + c1*k3
        ode_f2(ztA, ztB, kA, kB, s, i0, half);
#pragma unroll
        for (int j2 = 0; j2 < 4; j2++) {
            ulonglong2 a = znb[tid][j2], b = znb[tid][j2 + 4];
            a.x = ffma2(c3, kA[2*j2], a.x);   a.y = ffma2(c3, kA[2*j2+1], a.y);
            b.x = ffma2(c3, kB[2*j2], b.x);   b.y = ffma2(c3, kB[2*j2+1], b.y);
            znb[tid][j2] = a; znb[tid][j2 + 4] = b;
        }
#pragma unroll
        for (int j = 0; j < 8; j++) {
            ztA[j] = ffma2(c1, kA[j], zA[j]);
            ztB[j] = ffma2(c1, kB[j], zB[j]);
        }

        // stage 4: z = zn + c6*k4
        ode_f2(ztA, ztB, kA, kB, s, i0, half);
#pragma unroll
        for (int j2 = 0; j2 < 4; j2++) {
            ulonglong2 a = znb[tid][j2], b = znb[tid][j2 + 4];
            zA[2*j2]   = ffma2(c6, kA[2*j2],   a.x);
            zA[2*j2+1] = ffma2(c6, kA[2*j2+1], a.y);
            zB[2*j2]   = ffma2(c6, kB[2*j2],   b.x);
            zB[2*j2+1] = ffma2(c6, kB[2*j2+1], b.y);
        }

        float2 y = decode2(zA, zB, s, i0, half);
        if (half == 0) {
            size_t base = (size_t)(st + 1) * Bn;
            if (vA) out[base + eA] = y.x;
            if (vB) out[base + eB] = y.y;
        }
    }
}

extern "C" void kernel_launch(void* const* d_in, const int* in_sizes, int n_in,
                              void* d_out, int out_size) {
    const float* x0  = (const float*)d_in[0];
    const float* t   = (const float*)d_in[1];
    const float* We1 = (const float*)d_in[2];
    const float* be1 = (const float*)d_in[3];
    const float* We2 = (const float*)d_in[4];
    const float* be2 = (const float*)d_in[5];
    const float* Wo1 = (const float*)d_in[6];
    const float* bo1 = (const float*)d_in[7];
    const float* Wo2 = (const float*)d_in[8];
    const float* bo2 = (const float*)d_in[9];
    const float* Wd1 = (const float*)d_in[10];
    const float* bd1 = (const float*)d_in[11];
    const float* Wd2 = (const float*)d_in[12];
    const float* bd2 = (const float*)d_in[13];

    int Bn = in_sizes[0] / 2;   // x0 is (B, 2)
    int Tn = in_sizes[1];       // t is (T,)

    int threads = 64;                 // 2 warps; 32 elements per warp
    int blocks = (Bn + 63) / 64;      // 64 elements per block -> 1024 blocks
    node_kernel<<<blocks, threads>>>(x0, t, We1, be1, We2, be2, Wo1, bo1,
                                     Wo2, bo2, Wd1, bd1, Wd2, bd2,
                                     (float*)d_out, Bn, Tn);
}

// round 10
// speedup vs baseline: 1.0852x; 1.0852x over previous
#include <cuda_runtime.h>

// NeuralODE: encoder -> 99 RK4 steps -> decoder at every timestep.
// R3 structure (2 elements per thread, weight loads amortized) with the
// launch geometry fixed: 128-thread blocks. wid%4 -> SMSP, so 64-thread
// blocks only ever used sub-partitions 0 and 1 -- HALF the SM's schedulers
// and fma pipes sat idle in rounds 2-9 (hence issue pinned at ~53%).

#define HID 50
#define LAT 16

typedef unsigned long long u64;

__device__ __forceinline__ u64 pk2(float a, float b) {
    u64 v; asm("mov.b64 %0, {%1,%2};" : "=l"(v) : "f"(a), "f"(b)); return v;
}
__device__ __forceinline__ float2 up2(u64 v) {
    float2 r; asm("mov.b64 {%0,%1}, %2;" : "=f"(r.x), "=f"(r.y) : "l"(v)); return r;
}
__device__ __forceinline__ u64 ffma2(u64 a, u64 b, u64 c) {
    u64 d; asm("fma.rn.f32x2 %0, %1, %2, %3;" : "=l"(d) : "l"(a), "l"(b), "l"(c)); return d;
}
__device__ __forceinline__ u64 fmul2(u64 a, u64 b) {
    u64 d; asm("mul.rn.f32x2 %0, %1, %2;" : "=l"(d) : "l"(a), "l"(b)); return d;
}
__device__ __forceinline__ u64 fadd2(u64 a, u64 b) {
    u64 d; asm("add.rn.f32x2 %0, %1, %2;" : "=l"(d) : "l"(a), "l"(b)); return d;
}

// tanh(x) = 1 - 2/(1+e^{2x});  ~1e-6 rel err, saturates correctly.
__device__ __forceinline__ float tanh_fast(float x) {
    float e = __expf(2.0f * x);
    return 1.0f - __fdividef(2.0f, e + 1.0f);
}

struct __align__(16) SW {
    float wo1t[HID * LAT];  // wo1t[i*16+k] = Wo1[k][i]
    float wo2 [HID * LAT];  // Wo2[i][j], row-major
    float we2 [HID * LAT];  // We2[i][k], row-major
    float wd1t[HID * LAT];  // wd1t[i*16+k] = Wd1[k][i]
    float bo2[LAT];
    float be2[LAT];
    float bo1[HID];
    float be1[HID];
    float bd1[HID];
    float we1a[HID];        // We1[0][i]
    float we1b[HID];        // We1[1][i]
    float wd2[HID];
    float dt[128];
    float bd2;
};

// dot of 16-dim packed z with a weight row already in registers
__device__ __forceinline__ float rdot(const u64 zp[8], ulonglong2 w0, ulonglong2 w1,
                                      ulonglong2 w2, ulonglong2 w3) {
    u64 a0 = fmul2(zp[0], w0.x);
    u64 a1 = fmul2(zp[1], w0.y);
    a0 = ffma2(zp[2], w1.x, a0);
    a1 = ffma2(zp[3], w1.y, a1);
    a0 = ffma2(zp[4], w2.x, a0);
    a1 = ffma2(zp[5], w2.y, a1);
    a0 = ffma2(zp[6], w3.x, a0);
    a1 = ffma2(zp[7], w3.y, a1);
    float2 p = up2(fadd2(a0, a1));
    return p.x + p.y;
}

// k = tanh(z@Wo1 + bo1) @ Wo2 + bo2  for two elements sharing weight loads
__device__ __forceinline__ void ode_f2(const u64 zA[8], const u64 zB[8],
                                       u64 kA[8], u64 kB[8], const SW& s) {
    const u64* bo2p = (const u64*)s.bo2;
#pragma unroll
    for (int j = 0; j < 8; j++) { kA[j] = bo2p[j]; kB[j] = bo2p[j]; }
#pragma unroll 5
    for (int i = 0; i < HID; i++) {
        const ulonglong2* w = (const ulonglong2*)(s.wo1t + i * LAT);
        ulonglong2 w0 = w[0], w1 = w[1], w2 = w[2], w3 = w[3];
        float b1 = s.bo1[i];
        float hA = tanh_fast(rdot(zA, w0, w1, w2, w3) + b1);
        float hB = tanh_fast(rdot(zB, w0, w1, w2, w3) + b1);
        u64 hA2 = pk2(hA, hA), hB2 = pk2(hB, hB);
        const ulonglong2* v = (const ulonglong2*)(s.wo2 + i * LAT);
#pragma unroll
        for (int j = 0; j < 4; j++) {
            ulonglong2 vv = v[j];
            kA[2 * j]     = ffma2(hA2, vv.x, kA[2 * j]);
            kA[2 * j + 1] = ffma2(hA2, vv.y, kA[2 * j + 1]);
            kB[2 * j]     = ffma2(hB2, vv.x, kB[2 * j]);
            kB[2 * j + 1] = ffma2(hB2, vv.y, kB[2 * j + 1]);
        }
    }
}

// y = relu(z@Wd1 + bd1) @ Wd2 + bd2 for two elements sharing weight loads
__device__ __forceinline__ float2 decode2(const u64 zA[8], const u64 zB[8], const SW& s) {
    float yA = s.bd2, yB = s.bd2;
#pragma unroll 5
    for (int i = 0; i < HID; i++) {
        const ulonglong2* w = (const ulonglong2*)(s.wd1t + i * LAT);
        ulonglong2 w0 = w[0], w1 = w[1], w2 = w[2], w3 = w[3];
        float hA = fmaxf(rdot(zA, w0, w1, w2, w3) + s.bd1[i], 0.0f);
        float hB = fmaxf(rdot(zB, w0, w1, w2, w3) + s.bd1[i], 0.0f);
        float wd = s.wd2[i];
        yA = fmaf(hA, wd, yA);
        yB = fmaf(hB, wd, yB);
    }
    return make_float2(yA, yB);
}

__global__ void __launch_bounds__(128)
node_kernel(const float* __restrict__ x0, const float* __restrict__ t,
            const float* __restrict__ We1, const float* __restrict__ be1,
            const float* __restrict__ We2, const float* __restrict__ be2,
            const float* __restrict__ Wo1, const float* __restrict__ bo1,
            const float* __restrict__ Wo2, const float* __restrict__ bo2,
            const float* __restrict__ Wd1, const float* __restrict__ bd1,
            const float* __restrict__ Wd2, const float* __restrict__ bd2,
            float* __restrict__ out, int Bn, int Tn) {
    __shared__ SW s;
    int tid = threadIdx.x;

    for (int idx = tid; idx < HID * LAT; idx += blockDim.x) {
        int i = idx >> 4, k = idx & 15;
        s.wo1t[idx] = Wo1[k * HID + i];
        s.wd1t[idx] = Wd1[k * HID + i];
        s.wo2[idx]  = Wo2[idx];
        s.we2[idx]  = We2[idx];
    }
    for (int idx = tid; idx < HID; idx += blockDim.x) {
        s.bo1[idx]  = bo1[idx];
        s.be1[idx]  = be1[idx];
        s.bd1[idx]  = bd1[idx];
        s.we1a[idx] = We1[idx];
        s.we1b[idx] = We1[HID + idx];
        s.wd2[idx]  = Wd2[idx];
    }
    for (int idx = tid; idx < LAT; idx += blockDim.x) {
        s.bo2[idx] = bo2[idx];
        s.be2[idx] = be2[idx];
    }
    for (int idx = tid; idx < Tn - 1 && idx < 128; idx += blockDim.x)
        s.dt[idx] = t[idx + 1] - t[idx];
    if (tid == 0) s.bd2 = bd2[0];
    __syncthreads();

    int bA = blockIdx.x * 256 + tid;
    int bB = bA + 128;
    if (bA >= Bn) return;
    bool hasB = (bB < Bn);

    // ---------- Encoder for both elements (shared weight loads) ----------
    float2 xA = ((const float2*)x0)[bA];
    float2 xB = hasB ? ((const float2*)x0)[bB] : make_float2(0.f, 0.f);
    u64 zA[8], zB[8];
    {
        const u64* be2p = (const u64*)s.be2;
#pragma unroll
        for (int j = 0; j < 8; j++) { zA[j] = be2p[j]; zB[j] = be2p[j]; }
#pragma unroll 5
        for (int i = 0; i < HID; i++) {
            float w1a = s.we1a[i], w1b = s.we1b[i], b1 = s.be1[i];
            float hA = fmaxf(fmaf(xA.y, w1b, fmaf(xA.x, w1a, b1)), 0.0f);
            float hB = fmaxf(fmaf(xB.y, w1b, fmaf(xB.x, w1a, b1)), 0.0f);
            u64 hA2 = pk2(hA, hA), hB2 = pk2(hB, hB);
            const ulonglong2* w = (const ulonglong2*)(s.we2 + i * LAT);
#pragma unroll
            for (int j = 0; j < 4; j++) {
                ulonglong2 ww = w[j];
                zA[2 * j]     = ffma2(hA2, ww.x, zA[2 * j]);
                zA[2 * j + 1] = ffma2(hA2, ww.y, zA[2 * j + 1]);
                zB[2 * j]     = ffma2(hB2, ww.x, zB[2 * j]);
                zB[2 * j + 1] = ffma2(hB2, ww.y, zB[2 * j + 1]);
            }
        }
    }

    {
        float2 y = decode2(zA, zB, s);
        out[bA] = y.x;
        if (hasB) out[bB] = y.y;
    }

    // ---------- RK4 time stepping (stages fully unrolled) ----------
    for (int st = 0; st < Tn - 1; ++st) {
        float dt = s.dt[st];
        float h6 = dt * (1.0f / 6.0f);
        float h3 = dt * (1.0f / 3.0f);
        float hf = dt * 0.5f;
        u64 c6 = pk2(h6, h6), c3 = pk2(h3, h3), c2 = pk2(hf, hf), c1 = pk2(dt, dt);

        u64 znA[8], ztA[8], kkA[8];
        u64 znB[8], ztB[8], kkB[8];

        // stage 1
        ode_f2(zA, zB, kkA, kkB, s);
#pragma unroll
        for (int j = 0; j < 8; j++) {
            znA[j] = ffma2(c6, kkA[j], zA[j]);
            ztA[j] = ffma2(c2, kkA[j], zA[j]);
            znB[j] = ffma2(c6, kkB[j], zB[j]);
            ztB[j] = ffma2(c2, kkB[j], zB[j]);
        }
        // stage 2
        ode_f2(ztA, ztB, kkA, kkB, s);
#pragma unroll
        for (int j = 0; j < 8; j++) {
            znA[j] = ffma2(c3, kkA[j], znA[j]);
            ztA[j] = ffma2(c2, kkA[j], zA[j]);
            znB[j] = ffma2(c3, kkB[j], znB[j]);
            ztB[j] = ffma2(c2, kkB[j], zB[j]);
        }
        // stage 3
        ode_f2(ztA, ztB, kkA, kkB, s);
#pragma unroll
        for (int j = 0; j < 8; j++) {
            znA[j] = ffma2(c3, kkA[j], znA[j]);
            ztA[j] = ffma2(c1, kkA[j], zA[j]);
            znB[j] = ffma2(c3, kkB[j], znB[j]);
            ztB[j] = ffma2(c1, kkB[j], zB[j]);
        }
        // stage 4
        ode_f2(ztA, ztB, kkA, kkB, s);
#pragma unroll
        for (int j = 0; j < 8; j++) {
            zA[j] = ffma2(c6, kkA[j], znA[j]);
            zB[j] = ffma2(c6, kkB[j], znB[j]);
        }

        float2 y = decode2(zA, zB, s);
        size_t base = (size_t)(st + 1) * Bn;
        out[base + bA] = y.x;
        if (hasB) out[base + bB] = y.y;
    }
}

extern "C" void kernel_launch(void* const* d_in, const int* in_sizes, int n_in,
                              void* d_out, int out_size) {
    const float* x0  = (const float*)d_in[0];
    const float* t   = (const float*)d_in[1];
    const float* We1 = (const float*)d_in[2];
    const float* be1 = (const float*)d_in[3];
    const float* We2 = (const float*)d_in[4];
    const float* be2 = (const float*)d_in[5];
    const float* Wo1 = (const float*)d_in[6];
    const float* bo1 = (const float*)d_in[7];
    const float* Wo2 = (const float*)d_in[8];
    const float* bo2 = (const float*)d_in[9];
    const float* Wd1 = (const float*)d_in[10];
    const float* bd1 = (const float*)d_in[11];
    const float* Wd2 = (const float*)d_in[12];
    const float* bd2 = (const float*)d_in[13];

    int Bn = in_sizes[0] / 2;   // x0 is (B, 2)
    int Tn = in_sizes[1];       // t is (T,)

    int threads = 128;               // 4 warps -> all 4 SMSPs per block
    int blocks = (Bn + 255) / 256;   // 2 elements per thread
    node_kernel<<<blocks, threads>>>(x0, t, We1, be1, We2, be2, Wo1, bo1,
                                     Wo2, bo2, Wd1, bd1, Wd2, bd2,
                                     (float*)d_out, Bn, Tn);
}

// round 11
// speedup vs baseline: 1.2748x; 1.1747x over previous
#include <cuda_runtime.h>

// NeuralODE: encoder -> 99 RK4 steps -> decoder at every timestep.
// 2 elements/thread (E=2, best traffic config) + MUFU.TANH: the serial
// per-row chain LDS->dot->tanh->accum was ~95cyc with a 44-cyc 5-op tanh;
// hardware tanh.approx.f32 cuts it to 1 MUFU (16cyc) and removes ~14% of
// fma-pipe ops. unroll 10 gives ptxas 20 independent row chains.

#define HID 50
#define LAT 16

typedef unsigned long long u64;

__device__ __forceinline__ u64 pk2(float a, float b) {
    u64 v; asm("mov.b64 %0, {%1,%2};" : "=l"(v) : "f"(a), "f"(b)); return v;
}
__device__ __forceinline__ float2 up2(u64 v) {
    float2 r; asm("mov.b64 {%0,%1}, %2;" : "=f"(r.x), "=f"(r.y) : "l"(v)); return r;
}
__device__ __forceinline__ u64 ffma2(u64 a, u64 b, u64 c) {
    u64 d; asm("fma.rn.f32x2 %0, %1, %2, %3;" : "=l"(d) : "l"(a), "l"(b), "l"(c)); return d;
}
__device__ __forceinline__ u64 fmul2(u64 a, u64 b) {
    u64 d; asm("mul.rn.f32x2 %0, %1, %2;" : "=l"(d) : "l"(a), "l"(b)); return d;
}
__device__ __forceinline__ u64 fadd2(u64 a, u64 b) {
    u64 d; asm("add.rn.f32x2 %0, %1, %2;" : "=l"(d) : "l"(a), "l"(b)); return d;
}

// Hardware tanh (MUFU.TANH): 1 op, 16 cyc, ~2^-11 max abs err.
__device__ __forceinline__ float tanh_hw(float x) {
    float r; asm("tanh.approx.f32 %0, %1;" : "=f"(r) : "f"(x)); return r;
}

struct __align__(16) SW {
    float wo1t[HID * LAT];  // wo1t[i*16+k] = Wo1[k][i]
    float wo2 [HID * LAT];  // Wo2[i][j], row-major
    float we2 [HID * LAT];  // We2[i][k], row-major
    float wd1t[HID * LAT];  // wd1t[i*16+k] = Wd1[k][i]
    float bo2[LAT];
    float be2[LAT];
    float bo1[HID];
    float be1[HID];
    float bd1[HID];
    float we1a[HID];        // We1[0][i]
    float we1b[HID];        // We1[1][i]
    float wd2[HID];
    float dt[128];
    float bd2;
};

// dot of 16-dim packed z with a weight row already in registers
__device__ __forceinline__ float rdot(const u64 zp[8], ulonglong2 w0, ulonglong2 w1,
                                      ulonglong2 w2, ulonglong2 w3) {
    u64 a0 = fmul2(zp[0], w0.x);
    u64 a1 = fmul2(zp[1], w0.y);
    a0 = ffma2(zp[2], w1.x, a0);
    a1 = ffma2(zp[3], w1.y, a1);
    a0 = ffma2(zp[4], w2.x, a0);
    a1 = ffma2(zp[5], w2.y, a1);
    a0 = ffma2(zp[6], w3.x, a0);
    a1 = ffma2(zp[7], w3.y, a1);
    float2 p = up2(fadd2(a0, a1));
    return p.x + p.y;
}

// k = tanh(z@Wo1 + bo1) @ Wo2 + bo2  for two elements sharing weight loads
__device__ __forceinline__ void ode_f2(const u64 zA[8], const u64 zB[8],
                                       u64 kA[8], u64 kB[8], const SW& s) {
    const u64* bo2p = (const u64*)s.bo2;
#pragma unroll
    for (int j = 0; j < 8; j++) { kA[j] = bo2p[j]; kB[j] = bo2p[j]; }
#pragma unroll 10
    for (int i = 0; i < HID; i++) {
        const ulonglong2* w = (const ulonglong2*)(s.wo1t + i * LAT);
        ulonglong2 w0 = w[0], w1 = w[1], w2 = w[2], w3 = w[3];
        float b1 = s.bo1[i];
        float hA = tanh_hw(rdot(zA, w0, w1, w2, w3) + b1);
        float hB = tanh_hw(rdot(zB, w0, w1, w2, w3) + b1);
        u64 hA2 = pk2(hA, hA), hB2 = pk2(hB, hB);
        const ulonglong2* v = (const ulonglong2*)(s.wo2 + i * LAT);
#pragma unroll
        for (int j = 0; j < 4; j++) {
            ulonglong2 vv = v[j];
            kA[2 * j]     = ffma2(hA2, vv.x, kA[2 * j]);
            kA[2 * j + 1] = ffma2(hA2, vv.y, kA[2 * j + 1]);
            kB[2 * j]     = ffma2(hB2, vv.x, kB[2 * j]);
            kB[2 * j + 1] = ffma2(hB2, vv.y, kB[2 * j + 1]);
        }
    }
}

// y = relu(z@Wd1 + bd1) @ Wd2 + bd2 for two elements sharing weight loads
__device__ __forceinline__ float2 decode2(const u64 zA[8], const u64 zB[8], const SW& s) {
    float yA = s.bd2, yB = s.bd2;
#pragma unroll 10
    for (int i = 0; i < HID; i++) {
        const ulonglong2* w = (const ulonglong2*)(s.wd1t + i * LAT);
        ulonglong2 w0 = w[0], w1 = w[1], w2 = w[2], w3 = w[3];
        float hA = fmaxf(rdot(zA, w0, w1, w2, w3) + s.bd1[i], 0.0f);
        float hB = fmaxf(rdot(zB, w0, w1, w2, w3) + s.bd1[i], 0.0f);
        float wd = s.wd2[i];
        yA = fmaf(hA, wd, yA);
        yB = fmaf(hB, wd, yB);
    }
    return make_float2(yA, yB);
}

__global__ void __launch_bounds__(128)
node_kernel(const float* __restrict__ x0, const float* __restrict__ t,
            const float* __restrict__ We1, const float* __restrict__ be1,
            const float* __restrict__ We2, const float* __restrict__ be2,
            const float* __restrict__ Wo1, const float* __restrict__ bo1,
            const float* __restrict__ Wo2, const float* __restrict__ bo2,
            const float* __restrict__ Wd1, const float* __restrict__ bd1,
            const float* __restrict__ Wd2, const float* __restrict__ bd2,
            float* __restrict__ out, int Bn, int Tn) {
    __shared__ SW s;
    int tid = threadIdx.x;

    for (int idx = tid; idx < HID * LAT; idx += blockDim.x) {
        int i = idx >> 4, k = idx & 15;
        s.wo1t[idx] = Wo1[k * HID + i];
        s.wd1t[idx] = Wd1[k * HID + i];
        s.wo2[idx]  = Wo2[idx];
        s.we2[idx]  = We2[idx];
    }
    for (int idx = tid; idx < HID; idx += blockDim.x) {
        s.bo1[idx]  = bo1[idx];
        s.be1[idx]  = be1[idx];
        s.bd1[idx]  = bd1[idx];
        s.we1a[idx] = We1[idx];
        s.we1b[idx] = We1[HID + idx];
        s.wd2[idx]  = Wd2[idx];
    }
    for (int idx = tid; idx < LAT; idx += blockDim.x) {
        s.bo2[idx] = bo2[idx];
        s.be2[idx] = be2[idx];
    }
    for (int idx = tid; idx < Tn - 1 && idx < 128; idx += blockDim.x)
        s.dt[idx] = t[idx + 1] - t[idx];
    if (tid == 0) s.bd2 = bd2[0];
    __syncthreads();

    int bA = blockIdx.x * 256 + tid;
    int bB = bA + 128;
    if (bA >= Bn) return;
    bool hasB = (bB < Bn);

    // ---------- Encoder for both elements (shared weight loads) ----------
    float2 xA = ((const float2*)x0)[bA];
    float2 xB = hasB ? ((const float2*)x0)[bB] : make_float2(0.f, 0.f);
    u64 zA[8], zB[8];
    {
        const u64* be2p = (const u64*)s.be2;
#pragma unroll
        for (int j = 0; j < 8; j++) { zA[j] = be2p[j]; zB[j] = be2p[j]; }
#pragma unroll 10
        for (int i = 0; i < HID; i++) {
            float w1a = s.we1a[i], w1b = s.we1b[i], b1 = s.be1[i];
            float hA = fmaxf(fmaf(xA.y, w1b, fmaf(xA.x, w1a, b1)), 0.0f);
            float hB = fmaxf(fmaf(xB.y, w1b, fmaf(xB.x, w1a, b1)), 0.0f);
            u64 hA2 = pk2(hA, hA), hB2 = pk2(hB, hB);
            const ulonglong2* w = (const ulonglong2*)(s.we2 + i * LAT);
#pragma unroll
            for (int j = 0; j < 4; j++) {
                ulonglong2 ww = w[j];
                zA[2 * j]     = ffma2(hA2, ww.x, zA[2 * j]);
                zA[2 * j + 1] = ffma2(hA2, ww.y, zA[2 * j + 1]);
                zB[2 * j]     = ffma2(hB2, ww.x, zB[2 * j]);
                zB[2 * j + 1] = ffma2(hB2, ww.y, zB[2 * j + 1]);
            }
        }
    }

    {
        float2 y = decode2(zA, zB, s);
        out[bA] = y.x;
        if (hasB) out[bB] = y.y;
    }

    // ---------- RK4 time stepping (stages fully unrolled) ----------
    for (int st = 0; st < Tn - 1; ++st) {
        float dt = s.dt[st];
        float h6 = dt * (1.0f / 6.0f);
        float h3 = dt * (1.0f / 3.0f);
        float hf = dt * 0.5f;
        u64 c6 = pk2(h6, h6), c3 = pk2(h3, h3), c2 = pk2(hf, hf), c1 = pk2(dt, dt);

        u64 znA[8], ztA[8], kkA[8];
        u64 znB[8], ztB[8], kkB[8];

        // stage 1
        ode_f2(zA, zB, kkA, kkB, s);
#pragma unroll
        for (int j = 0; j < 8; j++) {
            znA[j] = ffma2(c6, kkA[j], zA[j]);
            ztA[j] = ffma2(c2, kkA[j], zA[j]);
            znB[j] = ffma2(c6, kkB[j], zB[j]);
            ztB[j] = ffma2(c2, kkB[j], zB[j]);
        }
        // stage 2
        ode_f2(ztA, ztB, kkA, kkB, s);
#pragma unroll
        for (int j = 0; j < 8; j++) {
            znA[j] = ffma2(c3, kkA[j], znA[j]);
            ztA[j] = ffma2(c2, kkA[j], zA[j]);
            znB[j] = ffma2(c3, kkB[j], znB[j]);
            ztB[j] = ffma2(c2, kkB[j], zB[j]);
        }
        // stage 3
        ode_f2(ztA, ztB, kkA, kkB, s);
#pragma unroll
        for (int j = 0; j < 8; j++) {
            znA[j] = ffma2(c3, kkA[j], znA[j]);
            ztA[j] = ffma2(c1, kkA[j], zA[j]);
            znB[j] = ffma2(c3, kkB[j], znB[j]);
            ztB[j] = ffma2(c1, kkB[j], zB[j]);
        }
        // stage 4
        ode_f2(ztA, ztB, kkA, kkB, s);
#pragma unroll
        for (int j = 0; j < 8; j++) {
            zA[j] = ffma2(c6, kkA[j], znA[j]);
            zB[j] = ffma2(c6, kkB[j], znB[j]);
        }

        float2 y = decode2(zA, zB, s);
        size_t base = (size_t)(st + 1) * Bn;
        out[base + bA] = y.x;
        if (hasB) out[base + bB] = y.y;
    }
}

extern "C" void kernel_launch(void* const* d_in, const int* in_sizes, int n_in,
                              void* d_out, int out_size) {
    const float* x0  = (const float*)d_in[0];
    const float* t   = (const float*)d_in[1];
    const float* We1 = (const float*)d_in[2];
    const float* be1 = (const float*)d_in[3];
    const float* We2 = (const float*)d_in[4];
    const float* be2 = (const float*)d_in[5];
    const float* Wo1 = (const float*)d_in[6];
    const float* bo1 = (const float*)d_in[7];
    const float* Wo2 = (const float*)d_in[8];
    const float* bo2 = (const float*)d_in[9];
    const float* Wd1 = (const float*)d_in[10];
    const float* bd1 = (const float*)d_in[11];
    const float* Wd2 = (const float*)d_in[12];
    const float* bd2 = (const float*)d_in[13];

    int Bn = in_sizes[0] / 2;   // x0 is (B, 2)
    int Tn = in_sizes[1];       // t is (T,)

    int threads = 128;
    int blocks = (Bn + 255) / 256;   // 2 elements per thread
    node_kernel<<<blocks, threads>>>(x0, t, We1, be1, We2, be2, Wo1, bo1,
                                     Wo2, bo2, Wd1, bd1, Wd2, bd2,
                                     (float*)d_out, Bn, Tn);
}